// round 8
// baseline (speedup 1.0000x reference)
#include <cuda_runtime.h>
#include <cuda_fp16.h>
#include <cstdint>

// Block-diagonal linear: y[n, b*64+j] = sum_{k<64} x[n, b*64+k] * w[b*64+j, b*64+k]
// fp16 m16n8k16 mma, 2-way hi/lo split, 3 terms (hh+hl+lh): ~3e-7 rel err.
// R8 (= R7 resubmit; R7 was an infra failure): barrier-free mainloop. A fragments
// loaded directly from global via LDG.128 using a k-permutation (lane tq owns
// semantic k 4tq..4tq+3); B fragments built with the same permutation, pinned in
// registers. W staged + split once per CTA.

#define N_FEAT   4096
#define BLK      64
#define NBLK     64
#define TROWS    64
#define MULTI    4
#define THREADS  256
#define XSP      36                 // u32 stride for W planes
#define RHALF    (BLK * XSP)

__device__ __forceinline__ void split_pack2(float a, float b, uint32_t& hi, uint32_t& lo) {
    __half2 H = __float22half2_rn(make_float2(a, b));   // 1x F2FP.PACK
    float2 f = __half22float2(H);
    __half2 L = __float22half2_rn(make_float2(a - f.x, b - f.y));
    hi = *(uint32_t*)&H;
    lo = *(uint32_t*)&L;
}

__device__ __forceinline__ void mma16816(float c[4],
                                         uint32_t a0, uint32_t a1, uint32_t a2, uint32_t a3,
                                         uint32_t b0, uint32_t b1) {
    asm volatile(
        "mma.sync.aligned.m16n8k16.row.col.f32.f16.f16.f32 "
        "{%0,%1,%2,%3}, {%4,%5,%6,%7}, {%8,%9}, {%0,%1,%2,%3};"
        : "+f"(c[0]), "+f"(c[1]), "+f"(c[2]), "+f"(c[3])
        : "r"(a0), "r"(a1), "r"(a2), "r"(a3), "r"(b0), "r"(b1));
}

__global__ __launch_bounds__(THREADS, 2)
void sl_blockdiag_kernel(const float* __restrict__ x,
                         const float* __restrict__ w,
                         float* __restrict__ out) {
    __shared__ uint32_t sW[2 * RHALF];      // hi plane, lo plane (f16x2 packed pairs)

    const int b  = blockIdx.x % NBLK;
    const int tg = blockIdx.x / NBLK;
    const int tid = threadIdx.x;
    const size_t colbase = (size_t)b * BLK;
    const size_t row0cta = (size_t)tg * (TROWS * MULTI);

    // ---- stage + split W_b once (u32 col j holds halves of k=2j, 2j+1) ----
    {
        uint32_t* wh = sW;
        uint32_t* wl = sW + RHALF;
        #pragma unroll
        for (int i = tid; i < BLK * 16; i += THREADS) {
            int r = i >> 4, q = i & 15;
            float4 v = *(const float4*)(w + (colbase + r) * N_FEAT + colbase + q * 4);
            uint32_t h0, l0, h1, l1;
            split_pack2(v.x, v.y, h0, l0);
            split_pack2(v.z, v.w, h1, l1);
            wh[r * XSP + 2 * q] = h0;  wh[r * XSP + 2 * q + 1] = h1;
            wl[r * XSP + 2 * q] = l0;  wl[r * XSP + 2 * q + 1] = l1;
        }
    }
    __syncthreads();

    const int wid  = tid >> 5;
    const int lane = tid & 31;
    const int g    = lane >> 2;    // groupID 0..7
    const int tq   = lane & 3;     // thread-in-group
    const int mg   = wid >> 1;     // 16-row group within tile
    const int nh   = wid & 1;      // 32-col half
    const int m0   = mg * 16;

    // ---- B fragments -> registers, same k-permutation as A:
    // b0 = halves of semantic k {16ks+4tq, +1}  -> u32 col 8ks+2tq
    // b1 = halves of semantic k {16ks+4tq+2,+3} -> u32 col 8ks+2tq+1
    uint32_t bh[4][4][2], bl[4][4][2];   // [nt][ks][reg]
    {
        const uint32_t* wh = sW;
        const uint32_t* wl = sW + RHALF;
        #pragma unroll
        for (int nt = 0; nt < 4; nt++) {
            int nrow = (nh * 4 + nt) * 8 + g;
            #pragma unroll
            for (int ks = 0; ks < 4; ks++) {
                int a = nrow * XSP + 8 * ks + 2 * tq;
                bh[nt][ks][0] = wh[a];  bh[nt][ks][1] = wh[a + 1];
                bl[nt][ks][0] = wl[a];  bl[nt][ks][1] = wl[a + 1];
            }
        }
    }

    // ---- barrier-free mainloop: A straight from global ----
    for (int t = 0; t < MULTI; t++) {
        const size_t rowg = row0cta + (size_t)t * TROWS + m0 + g;
        const float* xr0 = x + rowg * N_FEAT + colbase + tq * 4;        // row g
        const float* xr8 = xr0 + (size_t)8 * N_FEAT;                    // row g+8

        float c[4][4];
        #pragma unroll
        for (int i = 0; i < 4; i++)
            #pragma unroll
            for (int j = 0; j < 4; j++) c[i][j] = 0.f;

        #pragma unroll
        for (int ks = 0; ks < 4; ks++) {
            float4 va = *(const float4*)(xr0 + ks * 16);   // semantic k 16ks+4tq..+3, row g
            float4 vb = *(const float4*)(xr8 + ks * 16);   // row g+8

            uint32_t ah0, al0, ah2, al2, ah1, al1, ah3, al3;
            split_pack2(va.x, va.y, ah0, al0);   // a0: slots {2tq,2tq+1}
            split_pack2(va.z, va.w, ah2, al2);   // a2: slots {2tq+8,2tq+9}
            split_pack2(vb.x, vb.y, ah1, al1);   // a1: row g+8
            split_pack2(vb.z, vb.w, ah3, al3);   // a3

            #pragma unroll
            for (int nt = 0; nt < 4; nt++)
                mma16816(c[nt], ah0, ah1, ah2, ah3, bh[nt][ks][0], bh[nt][ks][1]);  // hh
            #pragma unroll
            for (int nt = 0; nt < 4; nt++)
                mma16816(c[nt], ah0, ah1, ah2, ah3, bl[nt][ks][0], bl[nt][ks][1]);  // hl
            #pragma unroll
            for (int nt = 0; nt < 4; nt++)
                mma16816(c[nt], al0, al1, al2, al3, bh[nt][ks][0], bh[nt][ks][1]);  // lh
        }

        // epilogue: C rows g/g+8, cols 2tq/2tq+1 per n-tile
        #pragma unroll
        for (int nt = 0; nt < 4; nt++) {
            size_t col = colbase + (nh * 4 + nt) * 8 + tq * 2;
            *(float2*)(out + rowg * N_FEAT + col)       = make_float2(c[nt][0], c[nt][1]);
            *(float2*)(out + (rowg + 8) * N_FEAT + col) = make_float2(c[nt][2], c[nt][3]);
        }
    }
}

extern "C" void kernel_launch(void* const* d_in, const int* in_sizes, int n_in,
                              void* d_out, int out_size) {
    const float* x = (const float*)d_in[0];
    const float* w = (const float*)d_in[1];
    float* out = (float*)d_out;

    const int n_rows = in_sizes[0] / N_FEAT;                 // 8192
    const int tile_groups = n_rows / (TROWS * MULTI);        // 32

    dim3 grid(NBLK * tile_groups);                           // 2048 CTAs
    sl_blockdiag_kernel<<<grid, THREADS>>>(x, w, out);
}

// round 9
// speedup vs baseline: 1.1423x; 1.1423x over previous
#include <cuda_runtime.h>
#include <cuda_fp16.h>
#include <cstdint>

// Block-diagonal linear: y[n, b*64+j] = sum_{k<64} x[n, b*64+k] * w[b*64+j, b*64+k]
// R9: fp16 m16n8k16, 2-term split y = (xh+xl)*wh  (w rounded to fp16: ~1.5e-4 rel err,
// tolerance is 1e-3). R5 structure: ldmatrix A frags, B pinned in regs, double-buffered
// X staging, deferred STG. 32 MMAs/tile/warp, ~80 regs -> 3 CTAs/SM.

#define N_FEAT   4096
#define BLK      64
#define NBLK     64
#define TROWS    64
#define MULTI    4
#define THREADS  256
#define XSP      36                 // u32 stride: (4r+c)%32 all distinct -> conflict-free
#define RHALF    (TROWS * XSP)      // u32 per plane

__device__ __forceinline__ void split_pack2(float a, float b, uint32_t& hi, uint32_t& lo) {
    __half2 H = __float22half2_rn(make_float2(a, b));
    float2 f = __half22float2(H);
    __half2 L = __float22half2_rn(make_float2(a - f.x, b - f.y));
    hi = *(uint32_t*)&H;
    lo = *(uint32_t*)&L;
}

__device__ __forceinline__ uint32_t pack_hi2(float a, float b) {
    __half2 H = __float22half2_rn(make_float2(a, b));
    return *(uint32_t*)&H;
}

__device__ __forceinline__ void mma16816(float c[4],
                                         uint32_t a0, uint32_t a1, uint32_t a2, uint32_t a3,
                                         uint32_t b0, uint32_t b1) {
    asm volatile(
        "mma.sync.aligned.m16n8k16.row.col.f32.f16.f16.f32 "
        "{%0,%1,%2,%3}, {%4,%5,%6,%7}, {%8,%9}, {%0,%1,%2,%3};"
        : "+f"(c[0]), "+f"(c[1]), "+f"(c[2]), "+f"(c[3])
        : "r"(a0), "r"(a1), "r"(a2), "r"(a3), "r"(b0), "r"(b1));
}

__device__ __forceinline__ void ldm_x4(uint32_t& r0, uint32_t& r1, uint32_t& r2, uint32_t& r3,
                                       uint32_t addr) {
    asm volatile("ldmatrix.sync.aligned.m8n8.x4.shared.b16 {%0,%1,%2,%3}, [%4];"
                 : "=r"(r0), "=r"(r1), "=r"(r2), "=r"(r3) : "r"(addr));
}

__global__ __launch_bounds__(THREADS, 3)
void sl_blockdiag_kernel(const float* __restrict__ x,
                         const float* __restrict__ w,
                         float* __restrict__ out) {
    __shared__ uint32_t smem[2][2 * RHALF];   // X double buffer (hi+lo planes); region 1 holds W first

    const int b  = blockIdx.x % NBLK;
    const int tg = blockIdx.x / NBLK;
    const int tid = threadIdx.x;
    const size_t colbase = (size_t)b * BLK;
    const size_t row0cta = (size_t)tg * (TROWS * MULTI);

    // ---- stage W_b hi-plane once into region 1 (fp16 round of w) ----
    {
        uint32_t* wh = smem[1];
        #pragma unroll
        for (int i = tid; i < BLK * 16; i += THREADS) {
            int r = i >> 4, q = i & 15;
            float4 v = *(const float4*)(w + (colbase + r) * N_FEAT + colbase + q * 4);
            wh[r * XSP + 2 * q]     = pack_hi2(v.x, v.y);
            wh[r * XSP + 2 * q + 1] = pack_hi2(v.z, v.w);
        }
    }
    __syncthreads();

    const int wid  = tid >> 5;
    const int lane = tid & 31;
    const int g    = lane >> 2;
    const int tq   = lane & 3;
    const int mg   = wid >> 1;
    const int nh   = wid & 1;
    const int m0   = mg * 16;

    // ---- B fragments (hi only) -> registers ----
    uint32_t bh[4][4][2];   // [nt][ks][reg]
    {
        const uint32_t* wh = smem[1];
        #pragma unroll
        for (int nt = 0; nt < 4; nt++) {
            int nrow = (nh * 4 + nt) * 8 + g;
            #pragma unroll
            for (int ks = 0; ks < 4; ks++) {
                int a = nrow * XSP + ks * 8 + tq;
                bh[nt][ks][0] = wh[a];
                bh[nt][ks][1] = wh[a + 4];
            }
        }
    }

    // ldmatrix lane -> address precompute (byte offset within a plane)
    const int lane7 = lane & 7;
    const int mat   = lane >> 3;
    const int arow  = m0 + lane7 + ((mat & 1) << 3);
    const int acolu = (mat >> 1) << 2;
    const uint32_t aoff = (uint32_t)(arow * XSP + acolu) * 4u;
    const uint32_t sb0  = (uint32_t)__cvta_generic_to_shared(&smem[0][0]);
    const uint32_t regbytes = 2u * RHALF * 4u;

    // staging coords
    const int sr = tid >> 2;
    const int sq = (tid & 3) * 4;

    // ---- stage X tile 0 (hi+lo split) into region 0 ----
    {
        const float4* src = (const float4*)(x + (row0cta + sr) * N_FEAT + colbase) + (tid & 3) * 4;
        uint32_t* xh = smem[0];
        uint32_t* xl = smem[0] + RHALF;
        #pragma unroll
        for (int j = 0; j < 4; j++) {
            float4 v = src[j];
            uint32_t h0, l0, h1, l1;
            split_pack2(v.x, v.y, h0, l0);
            split_pack2(v.z, v.w, h1, l1);
            int q = sq + j;
            xh[sr * XSP + 2 * q] = h0;  xh[sr * XSP + 2 * q + 1] = h1;
            xl[sr * XSP + 2 * q] = l0;  xl[sr * XSP + 2 * q + 1] = l1;
        }
    }
    __syncthreads();

    for (int t = 0; t < MULTI; t++) {
        // prefetch next tile into registers
        float4 p[4];
        if (t + 1 < MULTI) {
            const float4* src = (const float4*)(x + (row0cta + (t + 1) * TROWS + sr) * N_FEAT + colbase)
                                + (tid & 3) * 4;
            #pragma unroll
            for (int j = 0; j < 4; j++) p[j] = src[j];
        }

        const uint32_t tb = sb0 + (uint32_t)(t & 1) * regbytes;

        float c[4][4];
        #pragma unroll
        for (int i = 0; i < 4; i++)
            #pragma unroll
            for (int j = 0; j < 4; j++) c[i][j] = 0.f;

        #pragma unroll
        for (int ks = 0; ks < 4; ks++) {
            const uint32_t ab = tb + aoff + (uint32_t)(ks * 8) * 4u;
            uint32_t ah0, ah1, ah2, ah3, al0, al1, al2, al3;
            ldm_x4(ah0, ah1, ah2, ah3, ab);
            ldm_x4(al0, al1, al2, al3, ab + RHALF * 4u);

            #pragma unroll
            for (int nt = 0; nt < 4; nt++)
                mma16816(c[nt], ah0, ah1, ah2, ah3, bh[nt][ks][0], bh[nt][ks][1]);  // xh*wh
            #pragma unroll
            for (int nt = 0; nt < 4; nt++)
                mma16816(c[nt], al0, al1, al2, al3, bh[nt][ks][0], bh[nt][ks][1]);  // xl*wh
        }

        // split + store next tile (before the barrier)
        if (t + 1 < MULTI) {
            uint32_t* nxh = smem[(t + 1) & 1];
            uint32_t* nxl = nxh + RHALF;
            #pragma unroll
            for (int j = 0; j < 4; j++) {
                uint32_t h0, l0, h1, l1;
                split_pack2(p[j].x, p[j].y, h0, l0);
                split_pack2(p[j].z, p[j].w, h1, l1);
                int q = sq + j;
                nxh[sr * XSP + 2 * q] = h0;  nxh[sr * XSP + 2 * q + 1] = h1;
                nxl[sr * XSP + 2 * q] = l0;  nxl[sr * XSP + 2 * q + 1] = l1;
            }
            __syncthreads();
        }

        // epilogue AFTER the barrier: overlaps next tile's MMA
        const size_t row = row0cta + (size_t)t * TROWS + m0 + g;
        #pragma unroll
        for (int nt = 0; nt < 4; nt++) {
            size_t col = colbase + (nh * 4 + nt) * 8 + tq * 2;
            *(float2*)(out + row * N_FEAT + col)       = make_float2(c[nt][0], c[nt][1]);
            *(float2*)(out + (row + 8) * N_FEAT + col) = make_float2(c[nt][2], c[nt][3]);
        }
    }
}

extern "C" void kernel_launch(void* const* d_in, const int* in_sizes, int n_in,
                              void* d_out, int out_size) {
    const float* x = (const float*)d_in[0];
    const float* w = (const float*)d_in[1];
    float* out = (float*)d_out;

    const int n_rows = in_sizes[0] / N_FEAT;                 // 8192
    const int tile_groups = n_rows / (TROWS * MULTI);        // 32

    dim3 grid(NBLK * tile_groups);                           // 2048 CTAs
    sl_blockdiag_kernel<<<grid, THREADS>>>(x, w, out);
}

// round 10
// speedup vs baseline: 1.2494x; 1.0937x over previous
#include <cuda_runtime.h>
#include <cuda_fp16.h>
#include <cstdint>

// Block-diagonal linear: y[n, b*64+j] = sum_{k<64} x[n, b*64+k] * w[b*64+j, b*64+k]
// R10: pure fp16 m16n8k16 (both operands rounded once; fp32 accumulate).
// Predicted rel_err ~2.9e-4 vs 1e-3 tolerance (w-only rounding measured 2.08e-4).
// Structure from R5/R9: ldmatrix A frags, B pinned in regs, double-buffered X
// staging with STS.128, deferred STG. 16 MMAs/tile/warp.

#define N_FEAT   4096
#define BLK      64
#define NBLK     64
#define TROWS    64
#define MULTI    4
#define THREADS  256
#define XSP      36                 // u32 stride: conflict-free for ldmatrix + STS.128
#define PLANE    (TROWS * XSP)      // u32 per buffer (64 rows)

__device__ __forceinline__ uint32_t pack_h2(float a, float b) {
    __half2 H = __float22half2_rn(make_float2(a, b));
    return *(uint32_t*)&H;
}

__device__ __forceinline__ void mma16816(float c[4],
                                         uint32_t a0, uint32_t a1, uint32_t a2, uint32_t a3,
                                         uint32_t b0, uint32_t b1) {
    asm volatile(
        "mma.sync.aligned.m16n8k16.row.col.f32.f16.f16.f32 "
        "{%0,%1,%2,%3}, {%4,%5,%6,%7}, {%8,%9}, {%0,%1,%2,%3};"
        : "+f"(c[0]), "+f"(c[1]), "+f"(c[2]), "+f"(c[3])
        : "r"(a0), "r"(a1), "r"(a2), "r"(a3), "r"(b0), "r"(b1));
}

__device__ __forceinline__ void ldm_x4(uint32_t& r0, uint32_t& r1, uint32_t& r2, uint32_t& r3,
                                       uint32_t addr) {
    asm volatile("ldmatrix.sync.aligned.m8n8.x4.shared.b16 {%0,%1,%2,%3}, [%4];"
                 : "=r"(r0), "=r"(r1), "=r"(r2), "=r"(r3) : "r"(addr));
}

__global__ __launch_bounds__(THREADS, 3)
void sl_blockdiag_kernel(const float* __restrict__ x,
                         const float* __restrict__ w,
                         float* __restrict__ out) {
    __shared__ uint32_t smem[3][PLANE];   // [0],[1]: X double buffer; [2]: W

    const int b  = blockIdx.x % NBLK;
    const int tg = blockIdx.x / NBLK;
    const int tid = threadIdx.x;
    const size_t colbase = (size_t)b * BLK;
    const size_t row0cta = (size_t)tg * (TROWS * MULTI);

    // ---- stage W_b once (fp16 round), u32 col j holds k=2j,2j+1 ----
    {
        uint32_t* wh = smem[2];
        #pragma unroll
        for (int i = tid; i < BLK * 16; i += THREADS) {
            int r = i >> 4, q = i & 15;
            float4 v = *(const float4*)(w + (colbase + r) * N_FEAT + colbase + q * 4);
            wh[r * XSP + 2 * q]     = pack_h2(v.x, v.y);
            wh[r * XSP + 2 * q + 1] = pack_h2(v.z, v.w);
        }
    }
    __syncthreads();

    const int wid  = tid >> 5;
    const int lane = tid & 31;
    const int g    = lane >> 2;
    const int tq   = lane & 3;
    const int mg   = wid >> 1;
    const int nh   = wid & 1;
    const int m0   = mg * 16;

    // ---- B fragments -> registers (CTA lifetime) ----
    uint32_t bh[4][4][2];   // [nt][ks][reg]
    {
        const uint32_t* wh = smem[2];
        #pragma unroll
        for (int nt = 0; nt < 4; nt++) {
            int nrow = (nh * 4 + nt) * 8 + g;
            #pragma unroll
            for (int ks = 0; ks < 4; ks++) {
                int a = nrow * XSP + ks * 8 + tq;
                bh[nt][ks][0] = wh[a];
                bh[nt][ks][1] = wh[a + 4];
            }
        }
    }

    // ldmatrix lane -> address precompute (byte offset within a buffer)
    const int lane7 = lane & 7;
    const int mat   = lane >> 3;
    const int arow  = m0 + lane7 + ((mat & 1) << 3);
    const int acolu = (mat >> 1) << 2;
    const uint32_t aoff = (uint32_t)(arow * XSP + acolu) * 4u;
    const uint32_t sb0  = (uint32_t)__cvta_generic_to_shared(&smem[0][0]);
    const uint32_t bufbytes = (uint32_t)PLANE * 4u;

    // staging coords: row sr, float4 chunk (tid&3) -> u32 cols 2*sq..2*sq+7
    const int sr = tid >> 2;
    const int sq = (tid & 3) * 4;

    // ---- stage X tile 0 into buffer 0 ----
    {
        const float4* src = (const float4*)(x + (row0cta + sr) * N_FEAT + colbase) + (tid & 3) * 4;
        float4 v0 = src[0], v1 = src[1], v2 = src[2], v3 = src[3];
        uint32_t* dst = smem[0] + sr * XSP + 2 * sq;
        uint4 pa = make_uint4(pack_h2(v0.x, v0.y), pack_h2(v0.z, v0.w),
                              pack_h2(v1.x, v1.y), pack_h2(v1.z, v1.w));
        uint4 pb = make_uint4(pack_h2(v2.x, v2.y), pack_h2(v2.z, v2.w),
                              pack_h2(v3.x, v3.y), pack_h2(v3.z, v3.w));
        *(uint4*)(dst)     = pa;
        *(uint4*)(dst + 4) = pb;
    }
    __syncthreads();

    for (int t = 0; t < MULTI; t++) {
        // prefetch next tile into registers
        float4 p0, p1, p2, p3;
        if (t + 1 < MULTI) {
            const float4* src = (const float4*)(x + (row0cta + (t + 1) * TROWS + sr) * N_FEAT + colbase)
                                + (tid & 3) * 4;
            p0 = src[0]; p1 = src[1]; p2 = src[2]; p3 = src[3];
        }

        const uint32_t tb = sb0 + (uint32_t)(t & 1) * bufbytes;

        float c[4][4];
        #pragma unroll
        for (int i = 0; i < 4; i++)
            #pragma unroll
            for (int j = 0; j < 4; j++) c[i][j] = 0.f;

        #pragma unroll
        for (int ks = 0; ks < 4; ks++) {
            uint32_t a0, a1, a2, a3;
            ldm_x4(a0, a1, a2, a3, tb + aoff + (uint32_t)(ks * 8) * 4u);
            #pragma unroll
            for (int nt = 0; nt < 4; nt++)
                mma16816(c[nt], a0, a1, a2, a3, bh[nt][ks][0], bh[nt][ks][1]);
        }

        // pack + store next tile (before the barrier)
        if (t + 1 < MULTI) {
            uint32_t* dst = smem[(t + 1) & 1] + sr * XSP + 2 * sq;
            uint4 pa = make_uint4(pack_h2(p0.x, p0.y), pack_h2(p0.z, p0.w),
                                  pack_h2(p1.x, p1.y), pack_h2(p1.z, p1.w));
            uint4 pb = make_uint4(pack_h2(p2.x, p2.y), pack_h2(p2.z, p2.w),
                                  pack_h2(p3.x, p3.y), pack_h2(p3.z, p3.w));
            *(uint4*)(dst)     = pa;
            *(uint4*)(dst + 4) = pb;
            __syncthreads();
        }

        // epilogue AFTER the barrier: overlaps next tile's MMA
        const size_t row = row0cta + (size_t)t * TROWS + m0 + g;
        #pragma unroll
        for (int nt = 0; nt < 4; nt++) {
            size_t col = colbase + (nh * 4 + nt) * 8 + tq * 2;
            *(float2*)(out + row * N_FEAT + col)       = make_float2(c[nt][0], c[nt][1]);
            *(float2*)(out + (row + 8) * N_FEAT + col) = make_float2(c[nt][2], c[nt][3]);
        }
    }
}

extern "C" void kernel_launch(void* const* d_in, const int* in_sizes, int n_in,
                              void* d_out, int out_size) {
    const float* x = (const float*)d_in[0];
    const float* w = (const float*)d_in[1];
    float* out = (float*)d_out;

    const int n_rows = in_sizes[0] / N_FEAT;                 // 8192
    const int tile_groups = n_rows / (TROWS * MULTI);        // 32

    dim3 grid(NBLK * tile_groups);                           // 2048 CTAs
    sl_blockdiag_kernel<<<grid, THREADS>>>(x, w, out);
}